// round 11
// baseline (speedup 1.0000x reference)
#include <cuda_runtime.h>
#include <cstdint>

#define DEVINL __device__ __forceinline__

// ---------------- tile config ----------------
static constexpr int BM = 128, BN = 128, BK = 128;
static constexpr int STAGES = 3;
static constexpr int A_BYTES = BM * BK;                 // 16384
static constexpr int B_BYTES = BN * BK;                 // 16384
static constexpr int STAGE_BYTES = A_BYTES + B_BYTES;   // 32768

// smem layout: tensor region | scales | dp4a region | tile-broadcast slots
static constexpr int T_FRS  = STAGES * STAGE_BYTES;     // 98304
static constexpr int T_SBF  = T_FRS + 512;
static constexpr int D_BP   = 136;                      // dp4a B row stride: 8B-aligned, conflict-free
static constexpr int D_A    = BM * BK;                  // 16384
static constexpr int D_B    = BN * D_BP;                // 17408
static constexpr int D_STAGE = D_A + D_B;               // 33792
static constexpr int D_BASE = T_SBF + 512;              // 99328
static constexpr int SLOT_T = D_BASE + 3 * D_STAGE;     // tensor-half tile slot (4B)
static constexpr int SLOT_D = SLOT_T + 4;               // dp4a-half tile slot (4B)
static constexpr int SMEM_TOTAL = SLOT_D + 4 + 120;     // pad to 16B

static constexpr int MAX_M = 8192, MAX_K = 4096, MAX_N = 4096;

__device__ __align__(128) int8_t g_A8[(size_t)MAX_M * MAX_K];
__device__ __align__(128) int8_t g_B8[(size_t)MAX_N * MAX_K];
__device__ unsigned g_tile_ctr;        // shared tile pool; zeroed by cvt_all_kernel each launch

// ---------------- helpers ----------------
DEVINL uint32_t smem_u32(const void* p) {
    uint32_t a;
    asm("{ .reg .u64 t; cvta.to.shared.u64 t, %1; cvt.u32.u64 %0, t; }" : "=r"(a) : "l"(p));
    return a;
}
DEVINL void cp16(uint32_t s, const void* g) {
    asm volatile("cp.async.cg.shared.global [%0], [%1], 16;" :: "r"(s), "l"(g) : "memory");
}
DEVINL void cp4(uint32_t s, const void* g) {
    asm volatile("cp.async.ca.shared.global [%0], [%1], 4;" :: "r"(s), "l"(g) : "memory");
}
DEVINL void ldm_x4(uint32_t& r0, uint32_t& r1, uint32_t& r2, uint32_t& r3, uint32_t addr) {
    asm volatile("ldmatrix.sync.aligned.m8n8.x4.shared.b16 {%0,%1,%2,%3}, [%4];"
                 : "=r"(r0), "=r"(r1), "=r"(r2), "=r"(r3) : "r"(addr));
}
DEVINL void mma_s8(int* c, const uint32_t* a, const uint32_t* b) {
    asm volatile(
        "mma.sync.aligned.m16n8k32.row.col.s32.s8.s8.s32 "
        "{%0,%1,%2,%3}, {%4,%5,%6,%7}, {%8,%9}, {%0,%1,%2,%3};"
        : "+r"(c[0]), "+r"(c[1]), "+r"(c[2]), "+r"(c[3])
        : "r"(a[0]), "r"(a[1]), "r"(a[2]), "r"(a[3]), "r"(b[0]), "r"(b[1]));
}
DEVINL int dp4a_s32(int a, int b, int c) {
    int d;
    asm("dp4a.s32.s32 %0, %1, %2, %3;" : "=r"(d) : "r"(a), "r"(b), "r"(c));
    return d;
}
DEVINL void bar_t() { asm volatile("bar.sync 1, 256;" ::: "memory"); }  // tensor half
DEVINL void bar_d() { asm volatile("bar.sync 2, 256;" ::: "memory"); }  // dp4a half
DEVINL void cpwait1() { asm volatile("cp.async.wait_group 1;" ::: "memory"); }
DEVINL void cpcommit() { asm volatile("cp.async.commit_group;" ::: "memory"); }

// ---------------- int32 -> int8 repack + scale_out tail + counter reset ----------------
__global__ void cvt_all_kernel(const int4* __restrict__ A, const int4* __restrict__ B,
                               uint32_t* __restrict__ a8, uint32_t* __restrict__ b8,
                               int nA, int nB,
                               const float* __restrict__ so, float* __restrict__ tail, int nT) {
    int i = blockIdx.x * blockDim.x + threadIdx.x;
    if (i == 0) g_tile_ctr = 0;                       // reset pool every launch/replay
    if (i < nA) {
        int4 v = A[i];
        a8[i] = (uint32_t)(v.x & 255) | ((uint32_t)(v.y & 255) << 8) |
                ((uint32_t)(v.z & 255) << 16) | ((uint32_t)(v.w & 255) << 24);
    } else if (i < nA + nB) {
        int j = i - nA;
        int4 v = B[j];
        b8[j] = (uint32_t)(v.x & 255) | ((uint32_t)(v.y & 255) << 8) |
                ((uint32_t)(v.z & 255) << 16) | ((uint32_t)(v.w & 255) << 24);
    } else if (i < nA + nB + nT) {
        int j = i - nA - nB;
        tail[j] = so[j];
    }
}

// ---------------- hybrid persistent kernel, shared tile pool ----------------
// ARBITER-AWARE ROLE MAP (hi-wid-first issue arbitration):
//   warps 0-7  (tid < 256) : dp4a half  (latency-tolerant, soaks leftover issue slots)
//   warps 8-15 (tid >= 256): tensor half (scarce pipe, gets issue priority)
template <bool FOUT>
__global__ __launch_bounds__(512, 1) void hybrid_kernel(
    const float* __restrict__ scale_A, const float* __restrict__ scale_B,
    const float* __restrict__ scale_out, void* __restrict__ Cout,
    int M, int N, int K, int tilesM, int totalTiles)
{
    extern __shared__ __align__(1024) uint8_t smem[];
    const uint32_t sb = smem_u32(smem);
    const int tid = threadIdx.x;
    const int NT = K / BK;

    if (tid >= 256) {
        // ================= TENSOR HALF (warps 8-15: issue priority) =================
        const int tt = tid - 256;                          // 0..255 within half
        const int lane = tt & 31, wrp = tt >> 5;
        const int warpM = wrp >> 2, warpN = wrp & 3;       // 2x4 warps, 64x32 warp tile

        float* frs = reinterpret_cast<float*>(smem + T_FRS);
        float* sbf = reinterpret_cast<float*>(smem + T_SBF);
        volatile unsigned* slot = reinterpret_cast<volatile unsigned*>(smem + SLOT_T);

        const int rl = (lane & 7) | (((lane >> 3) & 1) << 3);
        const int kh = (lane >> 4) << 4;
        const uint32_t xorv = (uint32_t)((rl & 7) << 4);
        const uint32_t aRow = (uint32_t)((warpM * 64 + rl) * 128);
        const uint32_t bRow = (uint32_t)((warpN * 32 + rl) * 128);
        const int l4 = lane >> 2, lm = lane & 3;

        while (true) {
            if (tt == 0) *slot = atomicAdd(&g_tile_ctr, 1u);
            bar_t();
            const unsigned t = *slot;
            bar_t();
            if (t >= (unsigned)totalTiles) break;
            const int mt = (int)(t % (unsigned)tilesM), nt = (int)(t / (unsigned)tilesM);
            const int m0 = mt * BM, n0 = nt * BN;

            if (tt < 128) {
                frs[tt] = __fdiv_rn(scale_A[m0 + tt], scale_out[m0 + tt]);
                sbf[tt] = scale_B[n0 + tt];
            }
            const int8_t* gA0 = g_A8 + (size_t)m0 * K;
            const int8_t* gB0 = g_B8 + (size_t)n0 * K;

            auto produce = [&](int stage, int kt) {
                const int8_t* gA = gA0 + kt * BK;
                const int8_t* gB = gB0 + kt * BK;
                const uint32_t baseA = sb + (uint32_t)stage * STAGE_BYTES;
                const uint32_t baseB = baseA + A_BYTES;
#pragma unroll
                for (int i = 0; i < 4; i++) {
                    const int cid = i * 256 + tt;
                    const int row = cid >> 3, c16 = cid & 7;
                    const uint32_t so_ = (uint32_t)(row * 128) + (uint32_t)((c16 ^ (row & 7)) << 4);
                    cp16(baseA + so_, gA + (size_t)row * K + c16 * 16);
                }
#pragma unroll
                for (int i = 0; i < 4; i++) {
                    const int cid = i * 256 + tt;
                    const int row = cid >> 3, c16 = cid & 7;
                    const uint32_t so_ = (uint32_t)(row * 128) + (uint32_t)((c16 ^ (row & 7)) << 4);
                    cp16(baseB + so_, gB + (size_t)row * K + c16 * 16);
                }
                cpcommit();
            };

            int c[4][4][4];
#pragma unroll
            for (int mi = 0; mi < 4; mi++)
#pragma unroll
                for (int ni = 0; ni < 4; ni++)
#pragma unroll
                    for (int j = 0; j < 4; j++) c[mi][ni][j] = 0;

            produce(0, 0);
            produce(1, 1);
            cpwait1();
            bar_t();

            uint32_t a[2][4][4];
            uint32_t b[4][2];

            for (int kt = 0; kt < NT; kt++) {
                const uint32_t Ab = sb + (uint32_t)(kt % STAGES) * STAGE_BYTES;
                const uint32_t Bb = Ab + A_BYTES;
                {
                    const uint32_t kx0 = (uint32_t)kh ^ xorv;
#pragma unroll
                    for (int mi = 0; mi < 4; mi++)
                        ldm_x4(a[0][mi][0], a[0][mi][1], a[0][mi][2], a[0][mi][3],
                               Ab + aRow + (uint32_t)(mi * 2048) + kx0);
#pragma unroll
                    for (int nip = 0; nip < 2; nip++) {
                        uint32_t r0, r1, r2, r3;
                        ldm_x4(r0, r1, r2, r3, Bb + bRow + (uint32_t)(nip * 2048) + kx0);
                        b[2 * nip][0] = r0; b[2 * nip][1] = r2;
                        b[2 * nip + 1][0] = r1; b[2 * nip + 1][1] = r3;
                    }
                }
                const int kf = kt + STAGES - 1;
                if (kf < NT) produce(kf % STAGES, kf);
                else cpcommit();

#pragma unroll
                for (int ks = 0; ks < 4; ks++) {
                    if (ks < 3) {
                        const uint32_t kxn = (uint32_t)(((ks + 1) * 32 + kh)) ^ xorv;
#pragma unroll
                        for (int mi = 0; mi < 4; mi++)
                            ldm_x4(a[(ks + 1) & 1][mi][0], a[(ks + 1) & 1][mi][1],
                                   a[(ks + 1) & 1][mi][2], a[(ks + 1) & 1][mi][3],
                                   Ab + aRow + (uint32_t)(mi * 2048) + kxn);
                    }
#pragma unroll
                    for (int mi = 0; mi < 4; mi++)
#pragma unroll
                        for (int ni = 0; ni < 4; ni++)
                            mma_s8(c[mi][ni], a[ks & 1][mi], b[ni]);
                    if (ks < 3) {
                        const uint32_t kxn = (uint32_t)(((ks + 1) * 32 + kh)) ^ xorv;
#pragma unroll
                        for (int nip = 0; nip < 2; nip++) {
                            uint32_t r0, r1, r2, r3;
                            ldm_x4(r0, r1, r2, r3, Bb + bRow + (uint32_t)(nip * 2048) + kxn);
                            b[2 * nip][0] = r0; b[2 * nip][1] = r2;
                            b[2 * nip + 1][0] = r1; b[2 * nip + 1][1] = r3;
                        }
                    }
                }
                cpwait1();
                bar_t();
            }

            // epilogue: stage-0 region as staging
            uint8_t* stg = smem;
#pragma unroll
            for (int mi = 0; mi < 4; mi++) {
#pragma unroll
                for (int h = 0; h < 2; h++) {
                    const int row = warpM * 64 + mi * 16 + l4 + h * 8;
                    const float fr = frs[row];
#pragma unroll
                    for (int ni = 0; ni < 4; ni++) {
                        const int colb = warpN * 32 + ni * 8 + lm * 2;
                        const float s0 = sbf[colb], s1 = sbf[colb + 1];
                        const int acc0 = c[mi][ni][2 * h], acc1 = c[mi][ni][2 * h + 1];
                        float x0 = __fmul_rn(__fmul_rn((float)acc0, fr), s0);
                        float x1 = __fmul_rn(__fmul_rn((float)acc1, fr), s1);
                        int v0 = __float2int_rn(x0);
                        int v1 = __float2int_rn(x1);
                        v0 = v0 < -128 ? -128 : (v0 > 127 ? 127 : v0);
                        v1 = v1 < -128 ? -128 : (v1 > 127 ? 127 : v1);
                        const uint16_t pk = (uint16_t)((v0 & 255) | ((v1 & 255) << 8));
                        const int w = colb >> 2, bb = colb & 3;
                        *reinterpret_cast<uint16_t*>(
                            stg + row * 128 + ((w ^ (row & 31)) << 2) + bb) = pk;
                    }
                }
            }
            bar_t();
#pragma unroll
            for (int i = 0; i < 16; i++) {
                const int idx = i * 256 + tt;
                const int row = idx >> 5, w = idx & 31;
                const uint32_t v = *reinterpret_cast<const uint32_t*>(
                    stg + row * 128 + ((w ^ (row & 31)) << 2));
                if (FOUT) {
                    float4 f;
                    f.x = (float)(int)(int8_t)(v & 255);
                    f.y = (float)(int)(int8_t)((v >> 8) & 255);
                    f.z = (float)(int)(int8_t)((v >> 16) & 255);
                    f.w = (float)(int)(int8_t)((v >> 24) & 255);
                    *reinterpret_cast<float4*>(
                        (float*)Cout + (size_t)(m0 + row) * N + n0 + w * 4) = f;
                } else {
                    *reinterpret_cast<uint32_t*>(
                        (int8_t*)Cout + (size_t)(m0 + row) * N + n0 + w * 4) = v;
                }
            }
            bar_t();   // staging/stage-0 reusable next tile
        }
    } else {
        // ================= DP4A HALF (warps 0-7: fills leftover issue slots) =================
        const int tid2 = tid;                  // 0..255
        const int tx = tid2 & 15;              // cols tx + 16*j
        const int ty = tid2 >> 4;              // rows ty*8 + i

        const uint32_t DBASE = sb + D_BASE;
        volatile unsigned* slot = reinterpret_cast<volatile unsigned*>(smem + SLOT_D);

        while (true) {
            if (tid2 == 0) *slot = atomicAdd(&g_tile_ctr, 1u);
            bar_d();
            const unsigned t = *slot;
            bar_d();
            if (t >= (unsigned)totalTiles) break;
            const int mt = (int)(t % (unsigned)tilesM), nt = (int)(t / (unsigned)tilesM);
            const int m0 = mt * BM, n0 = nt * BN;
            const int8_t* gA0 = g_A8 + (size_t)m0 * K;
            const int8_t* gB0 = g_B8 + (size_t)n0 * K;

            auto produceD = [&](int stage, int kt) {
                const int8_t* gA = gA0 + kt * BK;
                const int8_t* gB = gB0 + kt * BK;
                const uint32_t baseA = DBASE + (uint32_t)stage * D_STAGE;
                const uint32_t baseB = baseA + D_A;
#pragma unroll
                for (int i = 0; i < 4; i++) {          // A: 1024 x 16B
                    const int cid = i * 256 + tid2;
                    const int row = cid >> 3, c16 = cid & 7;
                    cp16(baseA + (uint32_t)(row * 128 + c16 * 16),
                         gA + (size_t)row * K + c16 * 16);
                }
#pragma unroll
                for (int i = 0; i < 16; i++) {         // B: 4096 x 4B into 136B-padded rows
                    const int cid = i * 256 + tid2;
                    const int row = cid >> 5, w = cid & 31;
                    cp4(baseB + (uint32_t)(row * D_BP + w * 4),
                        gB + (size_t)row * K + w * 4);
                }
                cpcommit();
            };

            int acc[8][8];
#pragma unroll
            for (int i = 0; i < 8; i++)
#pragma unroll
                for (int j = 0; j < 8; j++) acc[i][j] = 0;

            produceD(0, 0);
            produceD(1, 1);

            for (int kt = 0; kt < NT; kt++) {
                cpwait1();
                bar_d();
                const int kf = kt + STAGES - 1;
                if (kf < NT) produceD(kf % STAGES, kf);
                else cpcommit();

                const uint8_t* As = smem + D_BASE + (size_t)(kt % STAGES) * D_STAGE
                                    + (size_t)(ty * 8) * 128;
                const uint8_t* Bs = smem + D_BASE + (size_t)(kt % STAGES) * D_STAGE + D_A
                                    + (size_t)tx * D_BP;
#pragma unroll 2
                for (int k8 = 0; k8 < 16; k8++) {      // 8 bytes of K per step, LDS.64
                    int2 av[8], bv[8];
#pragma unroll
                    for (int i = 0; i < 8; i++)
                        av[i] = *reinterpret_cast<const int2*>(As + i * 128 + k8 * 8);
#pragma unroll
                    for (int j = 0; j < 8; j++)
                        bv[j] = *reinterpret_cast<const int2*>(Bs + j * 16 * D_BP + k8 * 8);
#pragma unroll
                    for (int i = 0; i < 8; i++)
#pragma unroll
                        for (int j = 0; j < 8; j++) {
                            acc[i][j] = dp4a_s32(av[i].x, bv[j].x, acc[i][j]);
                            acc[i][j] = dp4a_s32(av[i].y, bv[j].y, acc[i][j]);
                        }
                }
            }

            // epilogue: direct global stores (lanes tx consecutive -> 64B segments)
            float sbj[8];
#pragma unroll
            for (int j = 0; j < 8; j++) sbj[j] = scale_B[n0 + tx + 16 * j];
#pragma unroll
            for (int i = 0; i < 8; i++) {
                const int rowg = m0 + ty * 8 + i;
                const float fr = __fdiv_rn(scale_A[rowg], scale_out[rowg]);
#pragma unroll
                for (int j = 0; j < 8; j++) {
                    float x = __fmul_rn(__fmul_rn((float)acc[i][j], fr), sbj[j]);
                    int v = __float2int_rn(x);
                    v = v < -128 ? -128 : (v > 127 ? 127 : v);
                    const size_t off = (size_t)rowg * N + n0 + tx + 16 * j;
                    if (FOUT) ((float*)Cout)[off] = (float)v;
                    else      ((int8_t*)Cout)[off] = (int8_t)v;
                }
            }
            bar_d();   // stages reusable next tile
        }
    }
}

// ---------------- launch ----------------
extern "C" void kernel_launch(void* const* d_in, const int* in_sizes, int n_in,
                              void* d_out, int out_size) {
    const int*   A  = (const int*)d_in[0];
    const float* sA = (const float*)d_in[1];
    const int*   B  = (const int*)d_in[2];
    const float* sB = (const float*)d_in[3];
    const float* so = (const float*)d_in[4];

    const int M = in_sizes[1];
    const int N = in_sizes[3];
    const int K = in_sizes[0] / M;

    void* pA = nullptr; void* pB = nullptr;
    cudaGetSymbolAddress(&pA, g_A8);
    cudaGetSymbolAddress(&pB, g_B8);

    const int nA = (M * K) / 4;
    const int nB = (N * K) / 4;
    const size_t MN = (size_t)M * N;
    const long long extra = (long long)out_size - (long long)MN;

    float* tail = nullptr;
    int nT = 0;
    if (extra == (long long)M) { tail = (float*)d_out + MN; nT = M; }
    else if (extra == (long long)4 * M) { tail = (float*)((int8_t*)d_out + MN); nT = M; }

    const int total = nA + nB + nT;
    cvt_all_kernel<<<(total + 511) / 512, 512>>>(
        (const int4*)A, (const int4*)B, (uint32_t*)pA, (uint32_t*)pB, nA, nB, so, tail, nT);

    int dev = 0, sms = 148;
    cudaGetDevice(&dev);
    cudaDeviceGetAttribute(&sms, cudaDevAttrMultiProcessorCount, dev);

    const int tilesM = M / BM, tilesN = N / BN;
    const int totalTiles = tilesM * tilesN;

    if (extra == (long long)M) {
        cudaFuncSetAttribute(hybrid_kernel<true>,
                             cudaFuncAttributeMaxDynamicSharedMemorySize, SMEM_TOTAL);
        hybrid_kernel<true><<<sms, 512, SMEM_TOTAL>>>(
            sA, sB, so, d_out, M, N, K, tilesM, totalTiles);
    } else {
        cudaFuncSetAttribute(hybrid_kernel<false>,
                             cudaFuncAttributeMaxDynamicSharedMemorySize, SMEM_TOTAL);
        hybrid_kernel<false><<<sms, 512, SMEM_TOTAL>>>(
            sA, sB, so, d_out, M, N, K, tilesM, totalTiles);
    }
}

// round 12
// speedup vs baseline: 1.0087x; 1.0087x over previous
#include <cuda_runtime.h>
#include <cstdint>

#define DEVINL __device__ __forceinline__

// ---------------- tile config ----------------
static constexpr int BM = 128, BN = 128, BK = 128;
static constexpr int STAGES = 3;
static constexpr int A_BYTES = BM * BK;                 // 16384
static constexpr int B_BYTES = BN * BK;                 // 16384
static constexpr int STAGE_BYTES = A_BYTES + B_BYTES;   // 32768

// smem layout: tensor stages | scales | epilogue staging | dp4a stages | slots
static constexpr int T_FRS  = STAGES * STAGE_BYTES;     // 98304
static constexpr int T_SBF  = T_FRS + 512;              // 98816
static constexpr int T_EPI  = T_SBF + 512;              // 99328 dedicated staging (16KB)
static constexpr int D_BP   = 136;                      // dp4a B row stride
static constexpr int D_A    = BM * BK;                  // 16384
static constexpr int D_B    = BN * D_BP;                // 17408
static constexpr int D_STAGE = D_A + D_B;               // 33792
static constexpr int D_BASE = T_EPI + 16384;            // 115712
static constexpr int SLOT_T = D_BASE + 3 * D_STAGE;     // 217088
static constexpr int SLOT_D = SLOT_T + 4;
static constexpr int SMEM_TOTAL = SLOT_D + 4 + 120;     // ~217.2KB (< 227KB cap)

static constexpr int MAX_M = 8192, MAX_K = 4096, MAX_N = 4096;

__device__ __align__(128) int8_t g_A8[(size_t)MAX_M * MAX_K];
__device__ __align__(128) int8_t g_B8[(size_t)MAX_N * MAX_K];
__device__ unsigned g_tile_ctr;        // shared tile pool; zeroed by cvt_all_kernel each launch

// ---------------- helpers ----------------
DEVINL uint32_t smem_u32(const void* p) {
    uint32_t a;
    asm("{ .reg .u64 t; cvta.to.shared.u64 t, %1; cvt.u32.u64 %0, t; }" : "=r"(a) : "l"(p));
    return a;
}
DEVINL void cp16(uint32_t s, const void* g) {
    asm volatile("cp.async.cg.shared.global [%0], [%1], 16;" :: "r"(s), "l"(g) : "memory");
}
DEVINL void cp4(uint32_t s, const void* g) {
    asm volatile("cp.async.ca.shared.global [%0], [%1], 4;" :: "r"(s), "l"(g) : "memory");
}
DEVINL void ldm_x4(uint32_t& r0, uint32_t& r1, uint32_t& r2, uint32_t& r3, uint32_t addr) {
    asm volatile("ldmatrix.sync.aligned.m8n8.x4.shared.b16 {%0,%1,%2,%3}, [%4];"
                 : "=r"(r0), "=r"(r1), "=r"(r2), "=r"(r3) : "r"(addr));
}
DEVINL void mma_s8(int* c, const uint32_t* a, const uint32_t* b) {
    asm volatile(
        "mma.sync.aligned.m16n8k32.row.col.s32.s8.s8.s32 "
        "{%0,%1,%2,%3}, {%4,%5,%6,%7}, {%8,%9}, {%0,%1,%2,%3};"
        : "+r"(c[0]), "+r"(c[1]), "+r"(c[2]), "+r"(c[3])
        : "r"(a[0]), "r"(a[1]), "r"(a[2]), "r"(a[3]), "r"(b[0]), "r"(b[1]));
}
DEVINL int dp4a_s32(int a, int b, int c) {
    int d;
    asm("dp4a.s32.s32 %0, %1, %2, %3;" : "=r"(d) : "r"(a), "r"(b), "r"(c));
    return d;
}
DEVINL void bar_t() { asm volatile("bar.sync 1, 256;" ::: "memory"); }  // tensor half
DEVINL void bar_d() { asm volatile("bar.sync 2, 256;" ::: "memory"); }  // dp4a half
DEVINL void cpwait1() { asm volatile("cp.async.wait_group 1;" ::: "memory"); }
DEVINL void cpcommit() { asm volatile("cp.async.commit_group;" ::: "memory"); }

// ---------------- int32 -> int8 repack + scale_out tail + counter reset ----------------
__global__ void cvt_all_kernel(const int4* __restrict__ A, const int4* __restrict__ B,
                               uint32_t* __restrict__ a8, uint32_t* __restrict__ b8,
                               int nA, int nB,
                               const float* __restrict__ so, float* __restrict__ tail, int nT) {
    int i = blockIdx.x * blockDim.x + threadIdx.x;
    if (i == 0) g_tile_ctr = 0;
    if (i < nA) {
        int4 v = A[i];
        a8[i] = (uint32_t)(v.x & 255) | ((uint32_t)(v.y & 255) << 8) |
                ((uint32_t)(v.z & 255) << 16) | ((uint32_t)(v.w & 255) << 24);
    } else if (i < nA + nB) {
        int j = i - nA;
        int4 v = B[j];
        b8[j] = (uint32_t)(v.x & 255) | ((uint32_t)(v.y & 255) << 8) |
                ((uint32_t)(v.z & 255) << 16) | ((uint32_t)(v.w & 255) << 24);
    } else if (i < nA + nB + nT) {
        int j = i - nA - nB;
        tail[j] = so[j];
    }
}

// ---------------- hybrid persistent kernel, continuous cross-tile pipeline ----------------
// warps 0-7 (tid<256): dp4a half; warps 8-15: tensor half. Shared tile pool.
template <bool FOUT>
__global__ __launch_bounds__(512, 1) void hybrid_kernel(
    const float* __restrict__ scale_A, const float* __restrict__ scale_B,
    const float* __restrict__ scale_out, void* __restrict__ Cout,
    int M, int N, int K, int tilesM, int totalTiles)
{
    extern __shared__ __align__(1024) uint8_t smem[];
    const uint32_t sb = smem_u32(smem);
    const int tid = threadIdx.x;
    const int NT = K / BK;   // 32

    if (tid >= 256) {
        // ================= TENSOR HALF =================
        const int tt = tid - 256;
        const int lane = tt & 31, wrp = tt >> 5;
        const int warpM = wrp >> 2, warpN = wrp & 3;       // 2x4 warps, 64x32 warp tile

        float* frs = reinterpret_cast<float*>(smem + T_FRS);
        float* sbf = reinterpret_cast<float*>(smem + T_SBF);
        volatile unsigned* slot = reinterpret_cast<volatile unsigned*>(smem + SLOT_T);

        const int rl = (lane & 7) | (((lane >> 3) & 1) << 3);
        const int kh = (lane >> 4) << 4;
        const uint32_t xorv = (uint32_t)((rl & 7) << 4);
        const uint32_t aRow = (uint32_t)((warpM * 64 + rl) * 128);
        const uint32_t bRow = (uint32_t)((warpN * 32 + rl) * 128);
        const int l4 = lane >> 2, lm = lane & 3;

        auto produceT = [&](int stage, const int8_t* gA, const int8_t* gB) {
            const uint32_t baseA = sb + (uint32_t)stage * STAGE_BYTES;
            const uint32_t baseB = baseA + A_BYTES;
#pragma unroll
            for (int i = 0; i < 4; i++) {
                const int cid = i * 256 + tt;
                const int row = cid >> 3, c16 = cid & 7;
                const uint32_t so_ = (uint32_t)(row * 128) + (uint32_t)((c16 ^ (row & 7)) << 4);
                cp16(baseA + so_, gA + (size_t)row * K + c16 * 16);
            }
#pragma unroll
            for (int i = 0; i < 4; i++) {
                const int cid = i * 256 + tt;
                const int row = cid >> 3, c16 = cid & 7;
                const uint32_t so_ = (uint32_t)(row * 128) + (uint32_t)((c16 ^ (row & 7)) << 4);
                cp16(baseB + so_, gB + (size_t)row * K + c16 * 16);
            }
            cpcommit();
        };

        // ---- initial tile grab ----
        if (tt == 0) *slot = atomicAdd(&g_tile_ctr, 1u);
        bar_t();
        unsigned t = *slot;
        bar_t();

        const int8_t* gA0 = nullptr;
        const int8_t* gB0 = nullptr;
        int s = 0, sp = 2;                               // rolling consume/produce stages
        if (t < (unsigned)totalTiles) {
            gA0 = g_A8 + (size_t)((int)(t % (unsigned)tilesM) * BM) * K;
            gB0 = g_B8 + (size_t)((int)(t / (unsigned)tilesM) * BN) * K;
            produceT(0, gA0, gB0);                       // kt=0
            produceT(1, gA0 + BK, gB0 + BK);             // kt=1
            cpwait1();
            bar_t();
        }

        while (t < (unsigned)totalTiles) {
            const int mt = (int)(t % (unsigned)tilesM), nt = (int)(t / (unsigned)tilesM);
            const int m0 = mt * BM, n0 = nt * BN;

            if (tt < 128) {
                frs[tt] = __fdiv_rn(scale_A[m0 + tt], scale_out[m0 + tt]);
                sbf[tt] = scale_B[n0 + tt];
            }

            int c[4][4][4];
#pragma unroll
            for (int mi = 0; mi < 4; mi++)
#pragma unroll
                for (int ni = 0; ni < 4; ni++)
#pragma unroll
                    for (int j = 0; j < 4; j++) c[mi][ni][j] = 0;

            uint32_t a[2][4][4];
            uint32_t b[4][2];
            unsigned tn = t;
            const int8_t* gA0n = gA0;
            const int8_t* gB0n = gB0;

            for (int kt = 0; kt < NT; kt++) {
                const uint32_t Ab = sb + (uint32_t)s * STAGE_BYTES;
                const uint32_t Bb = Ab + A_BYTES;

                // ks0 fragments first
                {
                    const uint32_t kx0 = (uint32_t)kh ^ xorv;
#pragma unroll
                    for (int mi = 0; mi < 4; mi++)
                        ldm_x4(a[0][mi][0], a[0][mi][1], a[0][mi][2], a[0][mi][3],
                               Ab + aRow + (uint32_t)(mi * 2048) + kx0);
#pragma unroll
                    for (int nip = 0; nip < 2; nip++) {
                        uint32_t r0, r1, r2, r3;
                        ldm_x4(r0, r1, r2, r3, Bb + bRow + (uint32_t)(nip * 2048) + kx0);
                        b[2 * nip][0] = r0; b[2 * nip][1] = r2;
                        b[2 * nip + 1][0] = r1; b[2 * nip + 1][1] = r3;
                    }
                }

                // produce for kt+2 (current tile, or next tile's kt 0/1)
                if (kt < NT - 2) {
                    produceT(sp, gA0 + (kt + 2) * BK, gB0 + (kt + 2) * BK);
                    if (kt == NT - 3 && tt == 0) *slot = atomicAdd(&g_tile_ctr, 1u);
                } else {
                    if (kt == NT - 2) {
                        tn = *slot;      // written at kt==NT-3, published by that kt's bar
                        if (tn < (unsigned)totalTiles) {
                            gA0n = g_A8 + (size_t)((int)(tn % (unsigned)tilesM) * BM) * K;
                            gB0n = g_B8 + (size_t)((int)(tn / (unsigned)tilesM) * BN) * K;
                        }
                    }
                    if (tn < (unsigned)totalTiles)
                        produceT(sp, gA0n + (kt + 2 - NT) * BK, gB0n + (kt + 2 - NT) * BK);
                    else
                        cpcommit();
                }

#pragma unroll
                for (int ks = 0; ks < 4; ks++) {
                    if (ks < 3) {
                        const uint32_t kxn = (uint32_t)(((ks + 1) * 32 + kh)) ^ xorv;
#pragma unroll
                        for (int mi = 0; mi < 4; mi++)
                            ldm_x4(a[(ks + 1) & 1][mi][0], a[(ks + 1) & 1][mi][1],
                                   a[(ks + 1) & 1][mi][2], a[(ks + 1) & 1][mi][3],
                                   Ab + aRow + (uint32_t)(mi * 2048) + kxn);
                    }
#pragma unroll
                    for (int mi = 0; mi < 4; mi++)
#pragma unroll
                        for (int ni = 0; ni < 4; ni++)
                            mma_s8(c[mi][ni], a[ks & 1][mi], b[ni]);
                    if (ks < 3) {
                        const uint32_t kxn = (uint32_t)(((ks + 1) * 32 + kh)) ^ xorv;
#pragma unroll
                        for (int nip = 0; nip < 2; nip++) {
                            uint32_t r0, r1, r2, r3;
                            ldm_x4(r0, r1, r2, r3, Bb + bRow + (uint32_t)(nip * 2048) + kxn);
                            b[2 * nip][0] = r0; b[2 * nip][1] = r2;
                            b[2 * nip + 1][0] = r1; b[2 * nip + 1][1] = r3;
                        }
                    }
                }

                cpwait1();
                bar_t();
                s  = (s  == 2) ? 0 : s + 1;
                sp = (sp == 2) ? 0 : sp + 1;
            }

            // ---- epilogue (dedicated staging; next tile's loads already in flight) ----
            uint8_t* stg = smem + T_EPI;
#pragma unroll
            for (int mi = 0; mi < 4; mi++) {
#pragma unroll
                for (int h = 0; h < 2; h++) {
                    const int row = warpM * 64 + mi * 16 + l4 + h * 8;
                    const float fr = frs[row];
#pragma unroll
                    for (int ni = 0; ni < 4; ni++) {
                        const int colb = warpN * 32 + ni * 8 + lm * 2;
                        const float s0 = sbf[colb], s1 = sbf[colb + 1];
                        const int acc0 = c[mi][ni][2 * h], acc1 = c[mi][ni][2 * h + 1];
                        float x0 = __fmul_rn(__fmul_rn((float)acc0, fr), s0);
                        float x1 = __fmul_rn(__fmul_rn((float)acc1, fr), s1);
                        int v0 = __float2int_rn(x0);
                        int v1 = __float2int_rn(x1);
                        v0 = v0 < -128 ? -128 : (v0 > 127 ? 127 : v0);
                        v1 = v1 < -128 ? -128 : (v1 > 127 ? 127 : v1);
                        const uint16_t pk = (uint16_t)((v0 & 255) | ((v1 & 255) << 8));
                        const int w = colb >> 2, bb = colb & 3;
                        *reinterpret_cast<uint16_t*>(
                            stg + row * 128 + ((w ^ (row & 31)) << 2) + bb) = pk;
                    }
                }
            }
            bar_t();
#pragma unroll
            for (int i = 0; i < 16; i++) {
                const int idx = i * 256 + tt;
                const int row = idx >> 5, w = idx & 31;
                const uint32_t v = *reinterpret_cast<const uint32_t*>(
                    stg + row * 128 + ((w ^ (row & 31)) << 2));
                if (FOUT) {
                    float4 f;
                    f.x = (float)(int)(int8_t)(v & 255);
                    f.y = (float)(int)(int8_t)((v >> 8) & 255);
                    f.z = (float)(int)(int8_t)((v >> 16) & 255);
                    f.w = (float)(int)(int8_t)((v >> 24) & 255);
                    *reinterpret_cast<float4*>(
                        (float*)Cout + (size_t)(m0 + row) * N + n0 + w * 4) = f;
                } else {
                    *reinterpret_cast<uint32_t*>(
                        (int8_t*)Cout + (size_t)(m0 + row) * N + n0 + w * 4) = v;
                }
            }
            bar_t();   // staging + frs/sbf reusable next tile

            t = tn; gA0 = gA0n; gB0 = gB0n;
        }
    } else {
        // ================= DP4A HALF =================
        const int tid2 = tid;                  // 0..255
        const int tx = tid2 & 15;              // cols tx + 16*j
        const int ty = tid2 >> 4;              // rows ty*8 + i

        const uint32_t DBASE = sb + D_BASE;
        volatile unsigned* slot = reinterpret_cast<volatile unsigned*>(smem + SLOT_D);

        auto produceD = [&](int stage, const int8_t* gA, const int8_t* gB) {
            const uint32_t baseA = DBASE + (uint32_t)stage * D_STAGE;
            const uint32_t baseB = baseA + D_A;
#pragma unroll
            for (int i = 0; i < 4; i++) {          // A: 1024 x 16B
                const int cid = i * 256 + tid2;
                const int row = cid >> 3, c16 = cid & 7;
                cp16(baseA + (uint32_t)(row * 128 + c16 * 16),
                     gA + (size_t)row * K + c16 * 16);
            }
#pragma unroll
            for (int i = 0; i < 16; i++) {         // B: 4096 x 4B into padded rows
                const int cid = i * 256 + tid2;
                const int row = cid >> 5, w = cid & 31;
                cp4(baseB + (uint32_t)(row * D_BP + w * 4),
                    gB + (size_t)row * K + w * 4);
            }
            cpcommit();
        };

        // ---- initial tile grab ----
        if (tid2 == 0) *slot = atomicAdd(&g_tile_ctr, 1u);
        bar_d();
        unsigned t = *slot;
        bar_d();

        const int8_t* gA0 = nullptr;
        const int8_t* gB0 = nullptr;
        int s = 0, sp = 2;
        if (t < (unsigned)totalTiles) {
            gA0 = g_A8 + (size_t)((int)(t % (unsigned)tilesM) * BM) * K;
            gB0 = g_B8 + (size_t)((int)(t / (unsigned)tilesM) * BN) * K;
            produceD(0, gA0, gB0);
            produceD(1, gA0 + BK, gB0 + BK);
        }

        while (t < (unsigned)totalTiles) {
            const int mt = (int)(t % (unsigned)tilesM), nt = (int)(t / (unsigned)tilesM);
            const int m0 = mt * BM, n0 = nt * BN;

            int acc[8][8];
#pragma unroll
            for (int i = 0; i < 8; i++)
#pragma unroll
                for (int j = 0; j < 8; j++) acc[i][j] = 0;

            unsigned tn = t;
            const int8_t* gA0n = gA0;
            const int8_t* gB0n = gB0;

            for (int kt = 0; kt < NT; kt++) {
                cpwait1();
                bar_d();

                if (kt < NT - 2) {
                    produceD(sp, gA0 + (kt + 2) * BK, gB0 + (kt + 2) * BK);
                    if (kt == NT - 3 && tid2 == 0) *slot = atomicAdd(&g_tile_ctr, 1u);
                } else {
                    if (kt == NT - 2) {
                        tn = *slot;
                        if (tn < (unsigned)totalTiles) {
                            gA0n = g_A8 + (size_t)((int)(tn % (unsigned)tilesM) * BM) * K;
                            gB0n = g_B8 + (size_t)((int)(tn / (unsigned)tilesM) * BN) * K;
                        }
                    }
                    if (tn < (unsigned)totalTiles)
                        produceD(sp, gA0n + (kt + 2 - NT) * BK, gB0n + (kt + 2 - NT) * BK);
                    else
                        cpcommit();
                }

                const uint8_t* As = smem + D_BASE + (size_t)s * D_STAGE
                                    + (size_t)(ty * 8) * 128;
                const uint8_t* Bs = smem + D_BASE + (size_t)s * D_STAGE + D_A
                                    + (size_t)tx * D_BP;
#pragma unroll 2
                for (int k8 = 0; k8 < 16; k8++) {      // 8 bytes of K per step, LDS.64
                    int2 av[8], bv[8];
#pragma unroll
                    for (int i = 0; i < 8; i++)
                        av[i] = *reinterpret_cast<const int2*>(As + i * 128 + k8 * 8);
#pragma unroll
                    for (int j = 0; j < 8; j++)
                        bv[j] = *reinterpret_cast<const int2*>(Bs + j * 16 * D_BP + k8 * 8);
#pragma unroll
                    for (int i = 0; i < 8; i++)
#pragma unroll
                        for (int j = 0; j < 8; j++) {
                            acc[i][j] = dp4a_s32(av[i].x, bv[j].x, acc[i][j]);
                            acc[i][j] = dp4a_s32(av[i].y, bv[j].y, acc[i][j]);
                        }
                }

                s  = (s  == 2) ? 0 : s + 1;
                sp = (sp == 2) ? 0 : sp + 1;
            }

            // ---- epilogue: direct global stores (next tile's loads already in flight) ----
            float sbj[8];
#pragma unroll
            for (int j = 0; j < 8; j++) sbj[j] = scale_B[n0 + tx + 16 * j];
#pragma unroll
            for (int i = 0; i < 8; i++) {
                const int rowg = m0 + ty * 8 + i;
                const float fr = __fdiv_rn(scale_A[rowg], scale_out[rowg]);
#pragma unroll
                for (int j = 0; j < 8; j++) {
                    float x = __fmul_rn(__fmul_rn((float)acc[i][j], fr), sbj[j]);
                    int v = __float2int_rn(x);
                    v = v < -128 ? -128 : (v > 127 ? 127 : v);
                    const size_t off = (size_t)rowg * N + n0 + tx + 16 * j;
                    if (FOUT) ((float*)Cout)[off] = (float)v;
                    else      ((int8_t*)Cout)[off] = (int8_t)v;
                }
            }

            t = tn; gA0 = gA0n; gB0 = gB0n;
        }
    }
}

// ---------------- launch ----------------
extern "C" void kernel_launch(void* const* d_in, const int* in_sizes, int n_in,
                              void* d_out, int out_size) {
    const int*   A  = (const int*)d_in[0];
    const float* sA = (const float*)d_in[1];
    const int*   B  = (const int*)d_in[2];
    const float* sB = (const float*)d_in[3];
    const float* so = (const float*)d_in[4];

    const int M = in_sizes[1];
    const int N = in_sizes[3];
    const int K = in_sizes[0] / M;

    void* pA = nullptr; void* pB = nullptr;
    cudaGetSymbolAddress(&pA, g_A8);
    cudaGetSymbolAddress(&pB, g_B8);

    const int nA = (M * K) / 4;
    const int nB = (N * K) / 4;
    const size_t MN = (size_t)M * N;
    const long long extra = (long long)out_size - (long long)MN;

    float* tail = nullptr;
    int nT = 0;
    if (extra == (long long)M) { tail = (float*)d_out + MN; nT = M; }
    else if (extra == (long long)4 * M) { tail = (float*)((int8_t*)d_out + MN); nT = M; }

    const int total = nA + nB + nT;
    cvt_all_kernel<<<(total + 511) / 512, 512>>>(
        (const int4*)A, (const int4*)B, (uint32_t*)pA, (uint32_t*)pB, nA, nB, so, tail, nT);

    int dev = 0, sms = 148;
    cudaGetDevice(&dev);
    cudaDeviceGetAttribute(&sms, cudaDevAttrMultiProcessorCount, dev);

    const int tilesM = M / BM, tilesN = N / BN;
    const int totalTiles = tilesM * tilesN;

    if (extra == (long long)M) {
        cudaFuncSetAttribute(hybrid_kernel<true>,
                             cudaFuncAttributeMaxDynamicSharedMemorySize, SMEM_TOTAL);
        hybrid_kernel<true><<<sms, 512, SMEM_TOTAL>>>(
            sA, sB, so, d_out, M, N, K, tilesM, totalTiles);
    } else {
        cudaFuncSetAttribute(hybrid_kernel<false>,
                             cudaFuncAttributeMaxDynamicSharedMemorySize, SMEM_TOTAL);
        hybrid_kernel<false><<<sms, 512, SMEM_TOTAL>>>(
            sA, sB, so, d_out, M, N, K, tilesM, totalTiles);
    }
}

// round 13
// speedup vs baseline: 1.0275x; 1.0186x over previous
#include <cuda_runtime.h>
#include <cstdint>

#define DEVINL __device__ __forceinline__

// ---------------- tile config ----------------
static constexpr int BM = 128, BN = 128, BK = 128;
static constexpr int STAGES = 3;
static constexpr int A_BYTES = BM * BK;                 // 16384
static constexpr int B_BYTES = BN * BK;                 // 16384
static constexpr int STAGE_BYTES = A_BYTES + B_BYTES;   // 32768

// smem layout: tensor stages | scales | epilogue staging | dp4a stages | slots
static constexpr int T_FRS  = STAGES * STAGE_BYTES;     // 98304
static constexpr int T_SBF  = T_FRS + 512;              // 98816
static constexpr int T_EPI  = T_SBF + 512;              // 99328 dedicated staging (16KB)
static constexpr int D_BP   = 144;                      // dp4a B row stride: 16B-aligned, LDS.128 conflict-free
static constexpr int D_A    = BM * BK;                  // 16384
static constexpr int D_B    = BN * D_BP;                // 18432
static constexpr int D_STAGE = D_A + D_B;               // 34816
static constexpr int D_BASE = T_EPI + 16384;            // 115712
static constexpr int SLOT_T = D_BASE + 3 * D_STAGE;     // 220160
static constexpr int SLOT_D = SLOT_T + 4;
static constexpr int SMEM_TOTAL = SLOT_D + 4 + 120;     // ~220.3KB (< 227KB cap)

static constexpr int MAX_M = 8192, MAX_K = 4096, MAX_N = 4096;

__device__ __align__(128) int8_t g_A8[(size_t)MAX_M * MAX_K];
__device__ __align__(128) int8_t g_B8[(size_t)MAX_N * MAX_K];
__device__ unsigned g_tile_ctr;        // shared tile pool; zeroed by cvt_all_kernel each launch

// ---------------- helpers ----------------
DEVINL uint32_t smem_u32(const void* p) {
    uint32_t a;
    asm("{ .reg .u64 t; cvta.to.shared.u64 t, %1; cvt.u32.u64 %0, t; }" : "=r"(a) : "l"(p));
    return a;
}
DEVINL void cp16(uint32_t s, const void* g) {
    asm volatile("cp.async.cg.shared.global [%0], [%1], 16;" :: "r"(s), "l"(g) : "memory");
}
DEVINL void ldm_x4(uint32_t& r0, uint32_t& r1, uint32_t& r2, uint32_t& r3, uint32_t addr) {
    asm volatile("ldmatrix.sync.aligned.m8n8.x4.shared.b16 {%0,%1,%2,%3}, [%4];"
                 : "=r"(r0), "=r"(r1), "=r"(r2), "=r"(r3) : "r"(addr));
}
DEVINL void mma_s8(int* c, const uint32_t* a, const uint32_t* b) {
    asm volatile(
        "mma.sync.aligned.m16n8k32.row.col.s32.s8.s8.s32 "
        "{%0,%1,%2,%3}, {%4,%5,%6,%7}, {%8,%9}, {%0,%1,%2,%3};"
        : "+r"(c[0]), "+r"(c[1]), "+r"(c[2]), "+r"(c[3])
        : "r"(a[0]), "r"(a[1]), "r"(a[2]), "r"(a[3]), "r"(b[0]), "r"(b[1]));
}
DEVINL int dp4a_s32(int a, int b, int c) {
    int d;
    asm("dp4a.s32.s32 %0, %1, %2, %3;" : "=r"(d) : "r"(a), "r"(b), "r"(c));
    return d;
}
DEVINL void bar_t() { asm volatile("bar.sync 1, 256;" ::: "memory"); }  // tensor half
DEVINL void bar_d() { asm volatile("bar.sync 2, 256;" ::: "memory"); }  // dp4a half
DEVINL void cpwait1() { asm volatile("cp.async.wait_group 1;" ::: "memory"); }
DEVINL void cpcommit() { asm volatile("cp.async.commit_group;" ::: "memory"); }

// ---------------- int32 -> int8 repack + scale_out tail + counter reset ----------------
__global__ void cvt_all_kernel(const int4* __restrict__ A, const int4* __restrict__ B,
                               uint32_t* __restrict__ a8, uint32_t* __restrict__ b8,
                               int nA, int nB,
                               const float* __restrict__ so, float* __restrict__ tail, int nT) {
    int i = blockIdx.x * blockDim.x + threadIdx.x;
    if (i == 0) g_tile_ctr = 0;
    if (i < nA) {
        int4 v = A[i];
        a8[i] = (uint32_t)(v.x & 255) | ((uint32_t)(v.y & 255) << 8) |
                ((uint32_t)(v.z & 255) << 16) | ((uint32_t)(v.w & 255) << 24);
    } else if (i < nA + nB) {
        int j = i - nA;
        int4 v = B[j];
        b8[j] = (uint32_t)(v.x & 255) | ((uint32_t)(v.y & 255) << 8) |
                ((uint32_t)(v.z & 255) << 16) | ((uint32_t)(v.w & 255) << 24);
    } else if (i < nA + nB + nT) {
        int j = i - nA - nB;
        tail[j] = so[j];
    }
}

// ---------------- hybrid persistent kernel, continuous cross-tile pipeline ----------------
// warps 0-7 (tid<256): dp4a half; warps 8-15: tensor half. Shared tile pool.
template <bool FOUT>
__global__ __launch_bounds__(512, 1) void hybrid_kernel(
    const float* __restrict__ scale_A, const float* __restrict__ scale_B,
    const float* __restrict__ scale_out, void* __restrict__ Cout,
    int M, int N, int K, int tilesM, int totalTiles)
{
    extern __shared__ __align__(1024) uint8_t smem[];
    const uint32_t sb = smem_u32(smem);
    const int tid = threadIdx.x;
    const int NT = K / BK;   // 32

    if (tid >= 256) {
        // ================= TENSOR HALF =================
        const int tt = tid - 256;
        const int lane = tt & 31, wrp = tt >> 5;
        const int warpM = wrp >> 2, warpN = wrp & 3;       // 2x4 warps, 64x32 warp tile

        float* frs = reinterpret_cast<float*>(smem + T_FRS);
        float* sbf = reinterpret_cast<float*>(smem + T_SBF);
        volatile unsigned* slot = reinterpret_cast<volatile unsigned*>(smem + SLOT_T);

        const int rl = (lane & 7) | (((lane >> 3) & 1) << 3);
        const int kh = (lane >> 4) << 4;
        const uint32_t xorv = (uint32_t)((rl & 7) << 4);
        const uint32_t aRow = (uint32_t)((warpM * 64 + rl) * 128);
        const uint32_t bRow = (uint32_t)((warpN * 32 + rl) * 128);
        const int l4 = lane >> 2, lm = lane & 3;

        auto produceT = [&](int stage, const int8_t* gA, const int8_t* gB) {
            const uint32_t baseA = sb + (uint32_t)stage * STAGE_BYTES;
            const uint32_t baseB = baseA + A_BYTES;
#pragma unroll
            for (int i = 0; i < 4; i++) {
                const int cid = i * 256 + tt;
                const int row = cid >> 3, c16 = cid & 7;
                const uint32_t so_ = (uint32_t)(row * 128) + (uint32_t)((c16 ^ (row & 7)) << 4);
                cp16(baseA + so_, gA + (size_t)row * K + c16 * 16);
            }
#pragma unroll
            for (int i = 0; i < 4; i++) {
                const int cid = i * 256 + tt;
                const int row = cid >> 3, c16 = cid & 7;
                const uint32_t so_ = (uint32_t)(row * 128) + (uint32_t)((c16 ^ (row & 7)) << 4);
                cp16(baseB + so_, gB + (size_t)row * K + c16 * 16);
            }
            cpcommit();
        };

        // ---- initial tile grab ----
        if (tt == 0) *slot = atomicAdd(&g_tile_ctr, 1u);
        bar_t();
        unsigned t = *slot;
        bar_t();

        const int8_t* gA0 = nullptr;
        const int8_t* gB0 = nullptr;
        int s = 0, sp = 2;                               // rolling consume/produce stages
        if (t < (unsigned)totalTiles) {
            gA0 = g_A8 + (size_t)((int)(t % (unsigned)tilesM) * BM) * K;
            gB0 = g_B8 + (size_t)((int)(t / (unsigned)tilesM) * BN) * K;
            produceT(0, gA0, gB0);                       // kt=0
            produceT(1, gA0 + BK, gB0 + BK);             // kt=1
            cpwait1();
            bar_t();
        }

        while (t < (unsigned)totalTiles) {
            const int mt = (int)(t % (unsigned)tilesM), nt = (int)(t / (unsigned)tilesM);
            const int m0 = mt * BM, n0 = nt * BN;

            if (tt < 128) {
                frs[tt] = __fdiv_rn(scale_A[m0 + tt], scale_out[m0 + tt]);
                sbf[tt] = scale_B[n0 + tt];
            }

            int c[4][4][4];
#pragma unroll
            for (int mi = 0; mi < 4; mi++)
#pragma unroll
                for (int ni = 0; ni < 4; ni++)
#pragma unroll
                    for (int j = 0; j < 4; j++) c[mi][ni][j] = 0;

            uint32_t a[2][4][4];
            uint32_t b[4][2];
            unsigned tn = t;
            const int8_t* gA0n = gA0;
            const int8_t* gB0n = gB0;

            for (int kt = 0; kt < NT; kt++) {
                const uint32_t Ab = sb + (uint32_t)s * STAGE_BYTES;
                const uint32_t Bb = Ab + A_BYTES;

                // ks0 fragments first
                {
                    const uint32_t kx0 = (uint32_t)kh ^ xorv;
#pragma unroll
                    for (int mi = 0; mi < 4; mi++)
                        ldm_x4(a[0][mi][0], a[0][mi][1], a[0][mi][2], a[0][mi][3],
                               Ab + aRow + (uint32_t)(mi * 2048) + kx0);
#pragma unroll
                    for (int nip = 0; nip < 2; nip++) {
                        uint32_t r0, r1, r2, r3;
                        ldm_x4(r0, r1, r2, r3, Bb + bRow + (uint32_t)(nip * 2048) + kx0);
                        b[2 * nip][0] = r0; b[2 * nip][1] = r2;
                        b[2 * nip + 1][0] = r1; b[2 * nip + 1][1] = r3;
                    }
                }

                // produce for kt+2 (current tile, or next tile's kt 0/1)
                if (kt < NT - 2) {
                    produceT(sp, gA0 + (kt + 2) * BK, gB0 + (kt + 2) * BK);
                    if (kt == NT - 3 && tt == 0) *slot = atomicAdd(&g_tile_ctr, 1u);
                } else {
                    if (kt == NT - 2) {
                        tn = *slot;      // written at kt==NT-3, published by that kt's bar
                        if (tn < (unsigned)totalTiles) {
                            gA0n = g_A8 + (size_t)((int)(tn % (unsigned)tilesM) * BM) * K;
                            gB0n = g_B8 + (size_t)((int)(tn / (unsigned)tilesM) * BN) * K;
                        }
                    }
                    if (tn < (unsigned)totalTiles)
                        produceT(sp, gA0n + (kt + 2 - NT) * BK, gB0n + (kt + 2 - NT) * BK);
                    else
                        cpcommit();
                }

#pragma unroll
                for (int ks = 0; ks < 4; ks++) {
                    if (ks < 3) {
                        const uint32_t kxn = (uint32_t)(((ks + 1) * 32 + kh)) ^ xorv;
#pragma unroll
                        for (int mi = 0; mi < 4; mi++)
                            ldm_x4(a[(ks + 1) & 1][mi][0], a[(ks + 1) & 1][mi][1],
                                   a[(ks + 1) & 1][mi][2], a[(ks + 1) & 1][mi][3],
                                   Ab + aRow + (uint32_t)(mi * 2048) + kxn);
                    }
#pragma unroll
                    for (int mi = 0; mi < 4; mi++)
#pragma unroll
                        for (int ni = 0; ni < 4; ni++)
                            mma_s8(c[mi][ni], a[ks & 1][mi], b[ni]);
                    if (ks < 3) {
                        const uint32_t kxn = (uint32_t)(((ks + 1) * 32 + kh)) ^ xorv;
#pragma unroll
                        for (int nip = 0; nip < 2; nip++) {
                            uint32_t r0, r1, r2, r3;
                            ldm_x4(r0, r1, r2, r3, Bb + bRow + (uint32_t)(nip * 2048) + kxn);
                            b[2 * nip][0] = r0; b[2 * nip][1] = r2;
                            b[2 * nip + 1][0] = r1; b[2 * nip + 1][1] = r3;
                        }
                    }
                }

                cpwait1();
                bar_t();
                s  = (s  == 2) ? 0 : s + 1;
                sp = (sp == 2) ? 0 : sp + 1;
            }

            // ---- epilogue (dedicated staging; next tile's loads already in flight) ----
            uint8_t* stg = smem + T_EPI;
#pragma unroll
            for (int mi = 0; mi < 4; mi++) {
#pragma unroll
                for (int h = 0; h < 2; h++) {
                    const int row = warpM * 64 + mi * 16 + l4 + h * 8;
                    const float fr = frs[row];
#pragma unroll
                    for (int ni = 0; ni < 4; ni++) {
                        const int colb = warpN * 32 + ni * 8 + lm * 2;
                        const float s0 = sbf[colb], s1 = sbf[colb + 1];
                        const int acc0 = c[mi][ni][2 * h], acc1 = c[mi][ni][2 * h + 1];
                        float x0 = __fmul_rn(__fmul_rn((float)acc0, fr), s0);
                        float x1 = __fmul_rn(__fmul_rn((float)acc1, fr), s1);
                        int v0 = __float2int_rn(x0);
                        int v1 = __float2int_rn(x1);
                        v0 = v0 < -128 ? -128 : (v0 > 127 ? 127 : v0);
                        v1 = v1 < -128 ? -128 : (v1 > 127 ? 127 : v1);
                        const uint16_t pk = (uint16_t)((v0 & 255) | ((v1 & 255) << 8));
                        const int w = colb >> 2, bb = colb & 3;
                        *reinterpret_cast<uint16_t*>(
                            stg + row * 128 + ((w ^ (row & 31)) << 2) + bb) = pk;
                    }
                }
            }
            bar_t();
#pragma unroll
            for (int i = 0; i < 16; i++) {
                const int idx = i * 256 + tt;
                const int row = idx >> 5, w = idx & 31;
                const uint32_t v = *reinterpret_cast<const uint32_t*>(
                    stg + row * 128 + ((w ^ (row & 31)) << 2));
                if (FOUT) {
                    float4 f;
                    f.x = (float)(int)(int8_t)(v & 255);
                    f.y = (float)(int)(int8_t)((v >> 8) & 255);
                    f.z = (float)(int)(int8_t)((v >> 16) & 255);
                    f.w = (float)(int)(int8_t)((v >> 24) & 255);
                    *reinterpret_cast<float4*>(
                        (float*)Cout + (size_t)(m0 + row) * N + n0 + w * 4) = f;
                } else {
                    *reinterpret_cast<uint32_t*>(
                        (int8_t*)Cout + (size_t)(m0 + row) * N + n0 + w * 4) = v;
                }
            }
            bar_t();   // staging + frs/sbf reusable next tile

            t = tn; gA0 = gA0n; gB0 = gB0n;
        }
    } else {
        // ================= DP4A HALF =================
        const int tid2 = tid;                  // 0..255
        const int tx = tid2 & 15;              // cols tx + 16*j
        const int ty = tid2 >> 4;              // rows ty*8 + i

        const uint32_t DBASE = sb + D_BASE;
        volatile unsigned* slot = reinterpret_cast<volatile unsigned*>(smem + SLOT_D);

        auto produceD = [&](int stage, const int8_t* gA, const int8_t* gB) {
            const uint32_t baseA = DBASE + (uint32_t)stage * D_STAGE;
            const uint32_t baseB = baseA + D_A;
#pragma unroll
            for (int i = 0; i < 4; i++) {          // A: 1024 x 16B, 128B rows
                const int cid = i * 256 + tid2;
                const int row = cid >> 3, c16 = cid & 7;
                cp16(baseA + (uint32_t)(row * 128 + c16 * 16),
                     gA + (size_t)row * K + c16 * 16);
            }
#pragma unroll
            for (int i = 0; i < 4; i++) {          // B: 1024 x 16B into 144B-padded rows
                const int cid = i * 256 + tid2;
                const int row = cid >> 3, c16 = cid & 7;
                cp16(baseB + (uint32_t)(row * D_BP + c16 * 16),
                     gB + (size_t)row * K + c16 * 16);
            }
            cpcommit();
        };

        // ---- initial tile grab ----
        if (tid2 == 0) *slot = atomicAdd(&g_tile_ctr, 1u);
        bar_d();
        unsigned t = *slot;
        bar_d();

        const int8_t* gA0 = nullptr;
        const int8_t* gB0 = nullptr;
        int s = 0, sp = 2;
        if (t < (unsigned)totalTiles) {
            gA0 = g_A8 + (size_t)((int)(t % (unsigned)tilesM) * BM) * K;
            gB0 = g_B8 + (size_t)((int)(t / (unsigned)tilesM) * BN) * K;
            produceD(0, gA0, gB0);
            produceD(1, gA0 + BK, gB0 + BK);
        }

        while (t < (unsigned)totalTiles) {
            const int mt = (int)(t % (unsigned)tilesM), nt = (int)(t / (unsigned)tilesM);
            const int m0 = mt * BM, n0 = nt * BN;

            int acc[8][8];
#pragma unroll
            for (int i = 0; i < 8; i++)
#pragma unroll
                for (int j = 0; j < 8; j++) acc[i][j] = 0;

            unsigned tn = t;
            const int8_t* gA0n = gA0;
            const int8_t* gB0n = gB0;

            for (int kt = 0; kt < NT; kt++) {
                cpwait1();
                bar_d();

                if (kt < NT - 2) {
                    produceD(sp, gA0 + (kt + 2) * BK, gB0 + (kt + 2) * BK);
                    if (kt == NT - 3 && tid2 == 0) *slot = atomicAdd(&g_tile_ctr, 1u);
                } else {
                    if (kt == NT - 2) {
                        tn = *slot;
                        if (tn < (unsigned)totalTiles) {
                            gA0n = g_A8 + (size_t)((int)(tn % (unsigned)tilesM) * BM) * K;
                            gB0n = g_B8 + (size_t)((int)(tn / (unsigned)tilesM) * BN) * K;
                        }
                    }
                    if (tn < (unsigned)totalTiles)
                        produceD(sp, gA0n + (kt + 2 - NT) * BK, gB0n + (kt + 2 - NT) * BK);
                    else
                        cpcommit();
                }

                const uint8_t* As = smem + D_BASE + (size_t)s * D_STAGE
                                    + (size_t)(ty * 8) * 128;
                const uint8_t* Bs = smem + D_BASE + (size_t)s * D_STAGE + D_A
                                    + (size_t)tx * D_BP;
                // LDS.128 mainloop: 16B of K per step; A is 2-address broadcast,
                // B lanes hit disjoint bank groups (stride 144 = 16B-aligned, spread)
#pragma unroll 2
                for (int k16 = 0; k16 < 8; k16++) {
                    int4 av[8];
#pragma unroll
                    for (int i = 0; i < 8; i++)
                        av[i] = *reinterpret_cast<const int4*>(As + i * 128 + k16 * 16);
#pragma unroll
                    for (int j = 0; j < 8; j++) {
                        const int4 bv = *reinterpret_cast<const int4*>(
                            Bs + j * 16 * D_BP + k16 * 16);
#pragma unroll
                        for (int i = 0; i < 8; i++) {
                            acc[i][j] = dp4a_s32(av[i].x, bv.x, acc[i][j]);
                            acc[i][j] = dp4a_s32(av[i].y, bv.y, acc[i][j]);
                            acc[i][j] = dp4a_s32(av[i].z, bv.z, acc[i][j]);
                            acc[i][j] = dp4a_s32(av[i].w, bv.w, acc[i][j]);
                        }
                    }
                }

                s  = (s  == 2) ? 0 : s + 1;
                sp = (sp == 2) ? 0 : sp + 1;
            }

            // ---- epilogue: direct global stores (next tile's loads already in flight) ----
            float sbj[8];
#pragma unroll
            for (int j = 0; j < 8; j++) sbj[j] = scale_B[n0 + tx + 16 * j];
#pragma unroll
            for (int i = 0; i < 8; i++) {
                const int rowg = m0 + ty * 8 + i;
                const float fr = __fdiv_rn(scale_A[rowg], scale_out[rowg]);
#pragma unroll
                for (int j = 0; j < 8; j++) {
                    float x = __fmul_rn(__fmul_rn((float)acc[i][j], fr), sbj[j]);
                    int v = __float2int_rn(x);
                    v = v < -128 ? -128 : (v > 127 ? 127 : v);
                    const size_t off = (size_t)rowg * N + n0 + tx + 16 * j;
                    if (FOUT) ((float*)Cout)[off] = (float)v;
                    else      ((int8_t*)Cout)[off] = (int8_t)v;
                }
            }

            t = tn; gA0 = gA0n; gB0 = gB0n;
        }
    }
}

// ---------------- launch ----------------
extern "C" void kernel_launch(void* const* d_in, const int* in_sizes, int n_in,
                              void* d_out, int out_size) {
    const int*   A  = (const int*)d_in[0];
    const float* sA = (const float*)d_in[1];
    const int*   B  = (const int*)d_in[2];
    const float* sB = (const float*)d_in[3];
    const float* so = (const float*)d_in[4];

    const int M = in_sizes[1];
    const int N = in_sizes[3];
    const int K = in_sizes[0] / M;

    void* pA = nullptr; void* pB = nullptr;
    cudaGetSymbolAddress(&pA, g_A8);
    cudaGetSymbolAddress(&pB, g_B8);

    const int nA = (M * K) / 4;
    const int nB = (N * K) / 4;
    const size_t MN = (size_t)M * N;
    const long long extra = (long long)out_size - (long long)MN;

    float* tail = nullptr;
    int nT = 0;
    if (extra == (long long)M) { tail = (float*)d_out + MN; nT = M; }
    else if (extra == (long long)4 * M) { tail = (float*)((int8_t*)d_out + MN); nT = M; }

    const int total = nA + nB + nT;
    cvt_all_kernel<<<(total + 511) / 512, 512>>>(
        (const int4*)A, (const int4*)B, (uint32_t*)pA, (uint32_t*)pB, nA, nB, so, tail, nT);

    int dev = 0, sms = 148;
    cudaGetDevice(&dev);
    cudaDeviceGetAttribute(&sms, cudaDevAttrMultiProcessorCount, dev);

    const int tilesM = M / BM, tilesN = N / BN;
    const int totalTiles = tilesM * tilesN;

    if (extra == (long long)M) {
        cudaFuncSetAttribute(hybrid_kernel<true>,
                             cudaFuncAttributeMaxDynamicSharedMemorySize, SMEM_TOTAL);
        hybrid_kernel<true><<<sms, 512, SMEM_TOTAL>>>(
            sA, sB, so, d_out, M, N, K, tilesM, totalTiles);
    } else {
        cudaFuncSetAttribute(hybrid_kernel<false>,
                             cudaFuncAttributeMaxDynamicSharedMemorySize, SMEM_TOTAL);
        hybrid_kernel<false><<<sms, 512, SMEM_TOTAL>>>(
            sA, sB, so, d_out, M, N, K, tilesM, totalTiles);
    }
}

// round 14
// speedup vs baseline: 1.0695x; 1.0410x over previous
#include <cuda_runtime.h>
#include <cstdint>

#define DEVINL __device__ __forceinline__

// ---------------- tile config ----------------
// Work unit: 128 (M) x 64 (N). K tile per stage: 128 bytes.
static constexpr int BM = 128, BUN = 64, BK = 128;
static constexpr int STAGES = 3;
static constexpr int A_BYTES = BM * BK;                 // 16384
static constexpr int B_BYTES = BUN * BK;                // 8192
static constexpr int STAGE_BYTES = A_BYTES + B_BYTES;   // 24576

// smem layout: tensor stages | scales | epilogue staging | dp4a stages | slots
static constexpr int T_FRS  = STAGES * STAGE_BYTES;     // 73728
static constexpr int T_SBF  = T_FRS + 512;              // 74240
static constexpr int T_EPI  = T_SBF + 512;              // 74752 staging (128x64 = 8KB)
static constexpr int D_BP   = 144;                      // dp4a B row stride (16B-aligned)
static constexpr int D_A    = BM * BK;                  // 16384
static constexpr int D_B    = BUN * D_BP;               // 9216
static constexpr int D_STAGE = D_A + D_B;               // 25600
static constexpr int D_BASE = T_EPI + 8192;             // 82944
static constexpr int SLOT_T = D_BASE + 3 * D_STAGE;     // 159744
static constexpr int SLOT_D = SLOT_T + 4;
static constexpr int SMEM_TOTAL = SLOT_D + 4 + 120;     // ~160KB (< 227KB cap)

static constexpr int MAX_M = 8192, MAX_K = 4096, MAX_N = 4096;

__device__ __align__(128) int8_t g_A8[(size_t)MAX_M * MAX_K];
__device__ __align__(128) int8_t g_B8[(size_t)MAX_N * MAX_K];
__device__ unsigned g_tile_ctr;        // shared unit pool; zeroed by cvt_all_kernel each launch

// ---------------- helpers ----------------
DEVINL uint32_t smem_u32(const void* p) {
    uint32_t a;
    asm("{ .reg .u64 t; cvta.to.shared.u64 t, %1; cvt.u32.u64 %0, t; }" : "=r"(a) : "l"(p));
    return a;
}
DEVINL void cp16(uint32_t s, const void* g) {
    asm volatile("cp.async.cg.shared.global [%0], [%1], 16;" :: "r"(s), "l"(g) : "memory");
}
DEVINL void ldm_x4(uint32_t& r0, uint32_t& r1, uint32_t& r2, uint32_t& r3, uint32_t addr) {
    asm volatile("ldmatrix.sync.aligned.m8n8.x4.shared.b16 {%0,%1,%2,%3}, [%4];"
                 : "=r"(r0), "=r"(r1), "=r"(r2), "=r"(r3) : "r"(addr));
}
DEVINL void mma_s8(int* c, const uint32_t* a, const uint32_t* b) {
    asm volatile(
        "mma.sync.aligned.m16n8k32.row.col.s32.s8.s8.s32 "
        "{%0,%1,%2,%3}, {%4,%5,%6,%7}, {%8,%9}, {%0,%1,%2,%3};"
        : "+r"(c[0]), "+r"(c[1]), "+r"(c[2]), "+r"(c[3])
        : "r"(a[0]), "r"(a[1]), "r"(a[2]), "r"(a[3]), "r"(b[0]), "r"(b[1]));
}
DEVINL int dp4a_s32(int a, int b, int c) {
    int d;
    asm("dp4a.s32.s32 %0, %1, %2, %3;" : "=r"(d) : "r"(a), "r"(b), "r"(c));
    return d;
}
DEVINL void bar_t() { asm volatile("bar.sync 1, 256;" ::: "memory"); }  // tensor half
DEVINL void bar_d() { asm volatile("bar.sync 2, 256;" ::: "memory"); }  // dp4a half
DEVINL void cpwait1() { asm volatile("cp.async.wait_group 1;" ::: "memory"); }
DEVINL void cpcommit() { asm volatile("cp.async.commit_group;" ::: "memory"); }

// ---------------- int32 -> int8 repack + scale_out tail + counter reset ----------------
__global__ void cvt_all_kernel(const int4* __restrict__ A, const int4* __restrict__ B,
                               uint32_t* __restrict__ a8, uint32_t* __restrict__ b8,
                               int nA, int nB,
                               const float* __restrict__ so, float* __restrict__ tail, int nT) {
    int i = blockIdx.x * blockDim.x + threadIdx.x;
    if (i == 0) g_tile_ctr = 0;
    if (i < nA) {
        int4 v = A[i];
        a8[i] = (uint32_t)(v.x & 255) | ((uint32_t)(v.y & 255) << 8) |
                ((uint32_t)(v.z & 255) << 16) | ((uint32_t)(v.w & 255) << 24);
    } else if (i < nA + nB) {
        int j = i - nA;
        int4 v = B[j];
        b8[j] = (uint32_t)(v.x & 255) | ((uint32_t)(v.y & 255) << 8) |
                ((uint32_t)(v.z & 255) << 16) | ((uint32_t)(v.w & 255) << 24);
    } else if (i < nA + nB + nT) {
        int j = i - nA - nB;
        tail[j] = so[j];
    }
}

// ---------------- hybrid persistent kernel, 128x64 units, shared pool ----------------
// warps 0-7 (tid<256): dp4a half; warps 8-15: tensor half.
template <bool FOUT>
__global__ __launch_bounds__(512, 1) void hybrid_kernel(
    const float* __restrict__ scale_A, const float* __restrict__ scale_B,
    const float* __restrict__ scale_out, void* __restrict__ Cout,
    int M, int N, int K, int tilesM, int totalU)
{
    extern __shared__ __align__(1024) uint8_t smem[];
    const uint32_t sb = smem_u32(smem);
    const int tid = threadIdx.x;
    const int NT = K / BK;   // 32

    if (tid >= 256) {
        // ================= TENSOR HALF =================
        const int tt = tid - 256;
        const int lane = tt & 31, wrp = tt >> 5;
        const int warpM = wrp >> 2, warpN = wrp & 3;       // 2x4 warps, 64x16 warp tile

        float* frs = reinterpret_cast<float*>(smem + T_FRS);
        float* sbf = reinterpret_cast<float*>(smem + T_SBF);
        volatile unsigned* slot = reinterpret_cast<volatile unsigned*>(smem + SLOT_T);

        const int rl = (lane & 7) | (((lane >> 3) & 1) << 3);
        const int kh = (lane >> 4) << 4;
        const uint32_t xorv = (uint32_t)((rl & 7) << 4);
        const uint32_t aRow = (uint32_t)((warpM * 64 + rl) * 128);
        const uint32_t bRow = (uint32_t)((warpN * 16 + rl) * 128);
        const int l4 = lane >> 2, lm = lane & 3;

        auto produceT = [&](int stage, const int8_t* gA, const int8_t* gB) {
            const uint32_t baseA = sb + (uint32_t)stage * STAGE_BYTES;
            const uint32_t baseB = baseA + A_BYTES;
#pragma unroll
            for (int i = 0; i < 4; i++) {                  // A: 128 rows x 128B
                const int cid = i * 256 + tt;
                const int row = cid >> 3, c16 = cid & 7;
                const uint32_t so_ = (uint32_t)(row * 128) + (uint32_t)((c16 ^ (row & 7)) << 4);
                cp16(baseA + so_, gA + (size_t)row * K + c16 * 16);
            }
#pragma unroll
            for (int i = 0; i < 2; i++) {                  // B: 64 rows x 128B
                const int cid = i * 256 + tt;
                const int row = cid >> 3, c16 = cid & 7;
                const uint32_t so_ = (uint32_t)(row * 128) + (uint32_t)((c16 ^ (row & 7)) << 4);
                cp16(baseB + so_, gB + (size_t)row * K + c16 * 16);
            }
            cpcommit();
        };

        // ---- initial unit grab ----
        if (tt == 0) *slot = atomicAdd(&g_tile_ctr, 1u);
        bar_t();
        unsigned t = *slot;
        bar_t();

        const int8_t* gA0 = nullptr;
        const int8_t* gB0 = nullptr;
        int s = 0, sp = 2;
        if (t < (unsigned)totalU) {
            gA0 = g_A8 + (size_t)((int)(t % (unsigned)tilesM) * BM) * K;
            gB0 = g_B8 + (size_t)((int)(t / (unsigned)tilesM) * BUN) * K;
            produceT(0, gA0, gB0);
            produceT(1, gA0 + BK, gB0 + BK);
            cpwait1();
            bar_t();
        }

        while (t < (unsigned)totalU) {
            const int mt = (int)(t % (unsigned)tilesM), nc = (int)(t / (unsigned)tilesM);
            const int m0 = mt * BM, n0 = nc * BUN;

            if (tt < 128) frs[tt] = __fdiv_rn(scale_A[m0 + tt], scale_out[m0 + tt]);
            if (tt < 64)  sbf[tt] = scale_B[n0 + tt];

            int c[4][2][4];
#pragma unroll
            for (int mi = 0; mi < 4; mi++)
#pragma unroll
                for (int ni = 0; ni < 2; ni++)
#pragma unroll
                    for (int j = 0; j < 4; j++) c[mi][ni][j] = 0;

            uint32_t a[2][4][4];
            uint32_t b[2][2];
            unsigned tn = t;
            const int8_t* gA0n = gA0;
            const int8_t* gB0n = gB0;

            for (int kt = 0; kt < NT; kt++) {
                const uint32_t Ab = sb + (uint32_t)s * STAGE_BYTES;
                const uint32_t Bb = Ab + A_BYTES;

                // ks0 fragments first
                {
                    const uint32_t kx0 = (uint32_t)kh ^ xorv;
#pragma unroll
                    for (int mi = 0; mi < 4; mi++)
                        ldm_x4(a[0][mi][0], a[0][mi][1], a[0][mi][2], a[0][mi][3],
                               Ab + aRow + (uint32_t)(mi * 2048) + kx0);
                    uint32_t r0, r1, r2, r3;
                    ldm_x4(r0, r1, r2, r3, Bb + bRow + kx0);
                    b[0][0] = r0; b[0][1] = r2;
                    b[1][0] = r1; b[1][1] = r3;
                }

                // produce for kt+2 (current unit, or next unit's kt 0/1)
                if (kt < NT - 2) {
                    produceT(sp, gA0 + (kt + 2) * BK, gB0 + (kt + 2) * BK);
                    if (kt == NT - 3 && tt == 0) *slot = atomicAdd(&g_tile_ctr, 1u);
                } else {
                    if (kt == NT - 2) {
                        tn = *slot;
                        if (tn < (unsigned)totalU) {
                            gA0n = g_A8 + (size_t)((int)(tn % (unsigned)tilesM) * BM) * K;
                            gB0n = g_B8 + (size_t)((int)(tn / (unsigned)tilesM) * BUN) * K;
                        }
                    }
                    if (tn < (unsigned)totalU)
                        produceT(sp, gA0n + (kt + 2 - NT) * BK, gB0n + (kt + 2 - NT) * BK);
                    else
                        cpcommit();
                }

#pragma unroll
                for (int ks = 0; ks < 4; ks++) {
                    if (ks < 3) {
                        const uint32_t kxn = (uint32_t)(((ks + 1) * 32 + kh)) ^ xorv;
#pragma unroll
                        for (int mi = 0; mi < 4; mi++)
                            ldm_x4(a[(ks + 1) & 1][mi][0], a[(ks + 1) & 1][mi][1],
                                   a[(ks + 1) & 1][mi][2], a[(ks + 1) & 1][mi][3],
                                   Ab + aRow + (uint32_t)(mi * 2048) + kxn);
                    }
#pragma unroll
                    for (int mi = 0; mi < 4; mi++)
#pragma unroll
                        for (int ni = 0; ni < 2; ni++)
                            mma_s8(c[mi][ni], a[ks & 1][mi], b[ni]);
                    if (ks < 3) {
                        const uint32_t kxn = (uint32_t)(((ks + 1) * 32 + kh)) ^ xorv;
                        uint32_t r0, r1, r2, r3;
                        ldm_x4(r0, r1, r2, r3, Bb + bRow + kxn);
                        b[0][0] = r0; b[0][1] = r2;
                        b[1][0] = r1; b[1][1] = r3;
                    }
                }

                cpwait1();
                bar_t();
                s  = (s  == 2) ? 0 : s + 1;
                sp = (sp == 2) ? 0 : sp + 1;
            }

            // ---- epilogue (dedicated 8KB staging; next unit's loads in flight) ----
            uint8_t* stg = smem + T_EPI;    // 128 rows x 64B, xor-swizzled words
#pragma unroll
            for (int mi = 0; mi < 4; mi++) {
#pragma unroll
                for (int h = 0; h < 2; h++) {
                    const int row = warpM * 64 + mi * 16 + l4 + h * 8;
                    const float fr = frs[row];
#pragma unroll
                    for (int ni = 0; ni < 2; ni++) {
                        const int colb = warpN * 16 + ni * 8 + lm * 2;
                        const float s0 = sbf[colb], s1 = sbf[colb + 1];
                        const int acc0 = c[mi][ni][2 * h], acc1 = c[mi][ni][2 * h + 1];
                        float x0 = __fmul_rn(__fmul_rn((float)acc0, fr), s0);
                        float x1 = __fmul_rn(__fmul_rn((float)acc1, fr), s1);
                        int v0 = __float2int_rn(x0);
                        int v1 = __float2int_rn(x1);
                        v0 = v0 < -128 ? -128 : (v0 > 127 ? 127 : v0);
                        v1 = v1 < -128 ? -128 : (v1 > 127 ? 127 : v1);
                        const uint16_t pk = (uint16_t)((v0 & 255) | ((v1 & 255) << 8));
                        const int w = colb >> 2, bb = colb & 3;   // w in [0,16)
                        *reinterpret_cast<uint16_t*>(
                            stg + row * 64 + ((w ^ (row & 15)) << 2) + bb) = pk;
                    }
                }
            }
            bar_t();
#pragma unroll
            for (int i = 0; i < 8; i++) {               // 128 rows x 16 words
                const int idx = i * 256 + tt;
                const int row = idx >> 4, w = idx & 15;
                const uint32_t v = *reinterpret_cast<const uint32_t*>(
                    stg + row * 64 + ((w ^ (row & 15)) << 2));
                if (FOUT) {
                    float4 f;
                    f.x = (float)(int)(int8_t)(v & 255);
                    f.y = (float)(int)(int8_t)((v >> 8) & 255);
                    f.z = (float)(int)(int8_t)((v >> 16) & 255);
                    f.w = (float)(int)(int8_t)((v >> 24) & 255);
                    *reinterpret_cast<float4*>(
                        (float*)Cout + (size_t)(m0 + row) * N + n0 + w * 4) = f;
                } else {
                    *reinterpret_cast<uint32_t*>(
                        (int8_t*)Cout + (size_t)(m0 + row) * N + n0 + w * 4) = v;
                }
            }
            bar_t();

            t = tn; gA0 = gA0n; gB0 = gB0n;
        }
    } else {
        // ================= DP4A HALF =================
        const int tid2 = tid;                  // 0..255
        const int tx = tid2 & 15;              // cols tx + 16*j, j<4
        const int ty = tid2 >> 4;              // rows ty*8 + i

        const uint32_t DBASE = sb + D_BASE;
        volatile unsigned* slot = reinterpret_cast<volatile unsigned*>(smem + SLOT_D);

        auto produceD = [&](int stage, const int8_t* gA, const int8_t* gB) {
            const uint32_t baseA = DBASE + (uint32_t)stage * D_STAGE;
            const uint32_t baseB = baseA + D_A;
#pragma unroll
            for (int i = 0; i < 4; i++) {          // A: 128 rows x 128B
                const int cid = i * 256 + tid2;
                const int row = cid >> 3, c16 = cid & 7;
                cp16(baseA + (uint32_t)(row * 128 + c16 * 16),
                     gA + (size_t)row * K + c16 * 16);
            }
#pragma unroll
            for (int i = 0; i < 2; i++) {          // B: 64 rows x 128B into 144B rows
                const int cid = i * 256 + tid2;
                const int row = cid >> 3, c16 = cid & 7;
                cp16(baseB + (uint32_t)(row * D_BP + c16 * 16),
                     gB + (size_t)row * K + c16 * 16);
            }
            cpcommit();
        };

        // ---- initial unit grab ----
        if (tid2 == 0) *slot = atomicAdd(&g_tile_ctr, 1u);
        bar_d();
        unsigned t = *slot;
        bar_d();

        const int8_t* gA0 = nullptr;
        const int8_t* gB0 = nullptr;
        int s = 0, sp = 2;
        if (t < (unsigned)totalU) {
            gA0 = g_A8 + (size_t)((int)(t % (unsigned)tilesM) * BM) * K;
            gB0 = g_B8 + (size_t)((int)(t / (unsigned)tilesM) * BUN) * K;
            produceD(0, gA0, gB0);
            produceD(1, gA0 + BK, gB0 + BK);
        }

        while (t < (unsigned)totalU) {
            const int mt = (int)(t % (unsigned)tilesM), nc = (int)(t / (unsigned)tilesM);
            const int m0 = mt * BM, n0 = nc * BUN;

            int acc[8][4];
#pragma unroll
            for (int i = 0; i < 8; i++)
#pragma unroll
                for (int j = 0; j < 4; j++) acc[i][j] = 0;

            unsigned tn = t;
            const int8_t* gA0n = gA0;
            const int8_t* gB0n = gB0;

            for (int kt = 0; kt < NT; kt++) {
                cpwait1();
                bar_d();

                if (kt < NT - 2) {
                    produceD(sp, gA0 + (kt + 2) * BK, gB0 + (kt + 2) * BK);
                    if (kt == NT - 3 && tid2 == 0) *slot = atomicAdd(&g_tile_ctr, 1u);
                } else {
                    if (kt == NT - 2) {
                        tn = *slot;
                        if (tn < (unsigned)totalU) {
                            gA0n = g_A8 + (size_t)((int)(tn % (unsigned)tilesM) * BM) * K;
                            gB0n = g_B8 + (size_t)((int)(tn / (unsigned)tilesM) * BUN) * K;
                        }
                    }
                    if (tn < (unsigned)totalU)
                        produceD(sp, gA0n + (kt + 2 - NT) * BK, gB0n + (kt + 2 - NT) * BK);
                    else
                        cpcommit();
                }

                const uint8_t* As = smem + D_BASE + (size_t)s * D_STAGE
                                    + (size_t)(ty * 8) * 128;
                const uint8_t* Bs = smem + D_BASE + (size_t)s * D_STAGE + D_A
                                    + (size_t)tx * D_BP;
#pragma unroll 2
                for (int k16 = 0; k16 < 8; k16++) {
                    int4 av[8];
#pragma unroll
                    for (int i = 0; i < 8; i++)
                        av[i] = *reinterpret_cast<const int4*>(As + i * 128 + k16 * 16);
#pragma unroll
                    for (int j = 0; j < 4; j++) {
                        const int4 bv = *reinterpret_cast<const int4*>(
                            Bs + j * 16 * D_BP + k16 * 16);
#pragma unroll
                        for (int i = 0; i < 8; i++) {
                            acc[i][j] = dp4a_s32(av[i].x, bv.x, acc[i][j]);
                            acc[i][j] = dp4a_s32(av[i].y, bv.y, acc[i][j]);
                            acc[i][j] = dp4a_s32(av[i].z, bv.z, acc[i][j]);
                            acc[i][j] = dp4a_s32(av[i].w, bv.w, acc[i][j]);
                        }
                    }
                }

                s  = (s  == 2) ? 0 : s + 1;
                sp = (sp == 2) ? 0 : sp + 1;
            }

            // ---- epilogue: direct global stores ----
            float sbj[4];
#pragma unroll
            for (int j = 0; j < 4; j++) sbj[j] = scale_B[n0 + tx + 16 * j];
#pragma unroll
            for (int i = 0; i < 8; i++) {
                const int rowg = m0 + ty * 8 + i;
                const float fr = __fdiv_rn(scale_A[rowg], scale_out[rowg]);
#pragma unroll
                for (int j = 0; j < 4; j++) {
                    float x = __fmul_rn(__fmul_rn((float)acc[i][j], fr), sbj[j]);
                    int v = __float2int_rn(x);
                    v = v < -128 ? -128 : (v > 127 ? 127 : v);
                    const size_t off = (size_t)rowg * N + n0 + tx + 16 * j;
                    if (FOUT) ((float*)Cout)[off] = (float)v;
                    else      ((int8_t*)Cout)[off] = (int8_t)v;
                }
            }

            t = tn; gA0 = gA0n; gB0 = gB0n;
        }
    }
}

// ---------------- launch ----------------
extern "C" void kernel_launch(void* const* d_in, const int* in_sizes, int n_in,
                              void* d_out, int out_size) {
    const int*   A  = (const int*)d_in[0];
    const float* sA = (const float*)d_in[1];
    const int*   B  = (const int*)d_in[2];
    const float* sB = (const float*)d_in[3];
    const float* so = (const float*)d_in[4];

    const int M = in_sizes[1];
    const int N = in_sizes[3];
    const int K = in_sizes[0] / M;

    void* pA = nullptr; void* pB = nullptr;
    cudaGetSymbolAddress(&pA, g_A8);
    cudaGetSymbolAddress(&pB, g_B8);

    const int nA = (M * K) / 4;
    const int nB = (N * K) / 4;
    const size_t MN = (size_t)M * N;
    const long long extra = (long long)out_size - (long long)MN;

    float* tail = nullptr;
    int nT = 0;
    if (extra == (long long)M) { tail = (float*)d_out + MN; nT = M; }
    else if (extra == (long long)4 * M) { tail = (float*)((int8_t*)d_out + MN); nT = M; }

    const int total = nA + nB + nT;
    cvt_all_kernel<<<(total + 511) / 512, 512>>>(
        (const int4*)A, (const int4*)B, (uint32_t*)pA, (uint32_t*)pB, nA, nB, so, tail, nT);

    int dev = 0, sms = 148;
    cudaGetDevice(&dev);
    cudaDeviceGetAttribute(&sms, cudaDevAttrMultiProcessorCount, dev);

    const int tilesM = M / BM;
    const int totalU = tilesM * (N / BUN);

    if (extra == (long long)M) {
        cudaFuncSetAttribute(hybrid_kernel<true>,
                             cudaFuncAttributeMaxDynamicSharedMemorySize, SMEM_TOTAL);
        hybrid_kernel<true><<<sms, 512, SMEM_TOTAL>>>(
            sA, sB, so, d_out, M, N, K, tilesM, totalU);
    } else {
        cudaFuncSetAttribute(hybrid_kernel<false>,
                             cudaFuncAttributeMaxDynamicSharedMemorySize, SMEM_TOTAL);
        hybrid_kernel<false><<<sms, 512, SMEM_TOTAL>>>(
            sA, sB, so, d_out, M, N, K, tilesM, totalU);
    }
}